// round 15
// baseline (speedup 1.0000x reference)
#include <cuda_runtime.h>
#include <cuda_fp16.h>
#include <stdint.h>

#define KD 768
#define ND 768

#define BM 128
#define BN 128
#define BK 64
#define KTILES (KD / BK)                // 12
#define NSTG 3
#define STG_BYTES (BM * BK + BN * BK)   // 16384
#define NWT 576                         // one 32x32 weight tile per block

// Scratch (device globals — no runtime allocation).
__device__ int8_t g_Wt[ND * KD];
__device__ int    g_bmode;              // bias dtype: 0=f32, 1=f16

// ===========================================================================
// dtype predicates (fixed 64-word sample -> identical mode in every block)
// mode: 0 = f32-of-ints, 1 = int32, 2 = packed int8.
// ===========================================================================
__device__ __forceinline__ bool ok_f32_int(uint32_t u) {
    float f = __uint_as_float(u);
    return isfinite(f) && f == rintf(f) && fabsf(f) <= 127.f;
}
__device__ __forceinline__ bool ok_i32(uint32_t u) {
    int v = (int)u;
    return v >= -128 && v <= 127;
}

// ===========================================================================
// prep_w: 576 blocks, one 32x32 W tile each (transpose -> g_Wt, any dtype).
// Block 0 also publishes the bias dtype.
// ===========================================================================
__global__ __launch_bounds__(256, 2)
void prep_w(const void* __restrict__ wp, const uint32_t* __restrict__ bias_w) {
    const int b = blockIdx.x;
    const int tid = threadIdx.x;

    uint32_t u = (tid < 64) ? ((const uint32_t*)wp)[tid] : 0u;
    const int cf = __syncthreads_count(tid < 64 && ok_f32_int(u));
    const int ci = __syncthreads_count(tid < 64 && ok_i32(u));
    const int mode = (cf >= 58) ? 0 : ((ci >= 58) ? 1 : 2);

    if (b == 0 && tid == 0) {
        int bcnt = 0;
#pragma unroll
        for (int i = 0; i < 16; i++) {
            float f = __uint_as_float(bias_w[i]);
            bcnt += (isfinite(f) &&
                     (f == 0.f || (fabsf(f) >= 1e-6f && fabsf(f) <= 100.f)));
        }
        g_bmode = (bcnt >= 14) ? 0 : 1;
    }

    __shared__ int8_t t[32][33];
    const int tx = tid & 31, ty = tid >> 5;          // 32 x 8
    const int nb = (b % (ND / 32)) * 32;
    const int kb = (b / (ND / 32)) * 32;
#pragma unroll
    for (int j = 0; j < 32; j += 8) {
        const int kk = kb + ty + j, nn = nb + tx;
        int8_t v;
        if (mode == 0)      v = (int8_t)__float2int_rn(((const float*)wp)[kk * ND + nn]);
        else if (mode == 1) v = (int8_t)(((const int*)wp)[kk * ND + nn]);
        else                v = ((const int8_t*)wp)[kk * ND + nn];
        t[ty + j][tx] = v;
    }
    __syncthreads();
#pragma unroll
    for (int j = 0; j < 32; j += 8)
        g_Wt[(size_t)(nb + ty + j) * KD + kb + tx] = t[tx][ty + j];
}

// ===========================================================================
// GEMM helpers
// ===========================================================================
__device__ __forceinline__ int swz(int row, int w) {
    return row * 16 + (w ^ (((row >> 1) & 3) << 2));
}

__device__ __forceinline__ float quantf(int acc, float alpha, float b) {
    float v = __fadd_rn(__fmul_rn((float)acc, alpha), b);
    float f = rintf(v);
    return fminf(fmaxf(f, -128.f), 127.f);
}

__device__ __forceinline__ uint32_t pack4(int a0, int a1, int a2, int a3) {
    return (uint32_t)(a0 & 255) | ((uint32_t)(a1 & 255) << 8) |
           ((uint32_t)(a2 & 255) << 16) | ((uint32_t)(a3 & 255) << 24);
}

#define LDSM4(r0, r1, r2, r3, addr) \
    asm volatile("ldmatrix.sync.aligned.m8n8.x4.shared.b16 {%0,%1,%2,%3}, [%4];" \
                 : "=r"(r0), "=r"(r1), "=r"(r2), "=r"(r3) : "r"(addr))

#define MMA_ROW(accrow, a, bfr)                                               \
    do {                                                                      \
        _Pragma("unroll")                                                     \
        for (int nt = 0; nt < 4; nt++) {                                      \
            asm volatile(                                                     \
                "mma.sync.aligned.m16n8k32.row.col.s32.s8.s8.s32 "            \
                "{%0,%1,%2,%3}, {%4,%5,%6,%7}, {%8,%9}, {%0,%1,%2,%3};"       \
                : "+r"((accrow)[nt][0]), "+r"((accrow)[nt][1]),               \
                  "+r"((accrow)[nt][2]), "+r"((accrow)[nt][3])                \
                : "r"((a)[0]), "r"((a)[1]), "r"((a)[2]), "r"((a)[3]),         \
                  "r"((bfr)[nt][0]), "r"((bfr)[nt][1]));                      \
        }                                                                     \
    } while (0)

// ===========================================================================
// Fused stage loader:
//   B: int8 from g_Wt via cp.async (as before).
//   A: xmode==2 -> cp.async from xp directly (already int8);
//      xmode 0/1 -> coalesced 128B/thread LDG f32/i32, convert in registers,
//                   STS.128 into the same swizzled int8 layout. STS ordering
//                   vs LDSM readers is provided by the k-tile __syncthreads
//                   (two barriers separate write at kt and read at kt+2).
// ===========================================================================
__device__ __forceinline__ void load_stage(uint32_t sbase, const void* __restrict__ xp,
                                           int m0, int n0, int s, int kt, int tid,
                                           int xmode) {
    const uint32_t sa = sbase + (uint32_t)s * STG_BYTES;
    const uint32_t sb = sa + BM * BK;
    const int8_t* gB = g_Wt + (size_t)n0 * KD + kt * BK;
#pragma unroll
    for (int i = 0; i < 2; i++) {
        const int id = tid * 2 + i;
        const int row = id >> 2, c = id & 3;
        asm volatile("cp.async.cg.shared.global [%0], [%1], 16;"
                     :: "r"(sb + 4u * swz(row, c * 4)),
                        "l"(gB + (size_t)row * KD + c * 16));
    }

    if (xmode == 2) {
        const int8_t* gA = (const int8_t*)xp + (size_t)m0 * KD + kt * BK;
#pragma unroll
        for (int i = 0; i < 2; i++) {
            const int id = tid * 2 + i;
            const int row = id >> 2, c = id & 3;
            asm volatile("cp.async.cg.shared.global [%0], [%1], 16;"
                         :: "r"(sa + 4u * swz(row, c * 4)),
                            "l"(gA + (size_t)row * KD + c * 16));
        }
    } else {
        // thread t: row = t>>1, 32 contiguous elements at col offset (t&1)*32
        const int row = tid >> 1;
        const int half = tid & 1;
        const size_t ebase = (size_t)(m0 + row) * KD + (size_t)kt * BK + half * 32;
#pragma unroll
        for (int s2 = 0; s2 < 2; s2++) {
            uint32_t p[4];
            if (xmode == 0) {
                const float4* src =
                    reinterpret_cast<const float4*>((const float*)xp + ebase) + s2 * 4;
#pragma unroll
                for (int v = 0; v < 4; v++) {
                    float4 f = __ldcs(src + v);
                    p[v] = pack4(__float2int_rn(f.x), __float2int_rn(f.y),
                                 __float2int_rn(f.z), __float2int_rn(f.w));
                }
            } else {
                const int4* src =
                    reinterpret_cast<const int4*>((const int*)xp + ebase) + s2 * 4;
#pragma unroll
                for (int v = 0; v < 4; v++) {
                    int4 f = __ldcs(src + v);
                    p[v] = pack4(f.x, f.y, f.z, f.w);
                }
            }
            const int c = half * 2 + s2;          // 16B chunk index 0..3
            asm volatile("st.shared.v4.b32 [%0], {%1,%2,%3,%4};"
                         :: "r"(sa + 4u * swz(row, c * 4)),
                            "r"(p[0]), "r"(p[1]), "r"(p[2]), "r"(p[3]));
        }
    }
    asm volatile("cp.async.commit_group;" ::: "memory");
}

__global__ __launch_bounds__(256, 2)
void gemm_q8(const void* __restrict__ xp, const void* __restrict__ bias_p,
             const float* __restrict__ alpha_p, float* __restrict__ out) {
    __shared__ int8_t smem[NSTG * STG_BYTES];  // 48 KB
    const uint32_t sbase = (uint32_t)__cvta_generic_to_shared(smem);

    const int tid  = threadIdx.x;

    // per-CTA x dtype detection (fixed sample -> identical everywhere)
    uint32_t uu = (tid < 64) ? ((const uint32_t*)xp)[tid] : 0u;
    const int cf = __syncthreads_count(tid < 64 && ok_f32_int(uu));
    const int ci = __syncthreads_count(tid < 64 && ok_i32(uu));
    const int xmode = (cf >= 58) ? 0 : ((ci >= 58) ? 1 : 2);

    const int lane = tid & 31;
    const int warp = tid >> 5;
    const int wm = warp & 1;                   // 2 warps along M (64 rows)
    const int wn = warp >> 1;                  // 4 warps along N (32 cols)
    const int m0 = blockIdx.y * BM;
    const int n0 = blockIdx.x * BN;
    const int r = lane >> 2;
    const int q = lane & 3;

    // Per-lane swizzled ldmatrix offsets (reused every k-tile).
    const int j  = lane & 7;
    const int mg = lane >> 3;
    uint32_t offA[4][2], offB[2][2];
#pragma unroll
    for (int mt = 0; mt < 4; mt++) {
        const int rowA = wm * 64 + mt * 16 + (mg & 1) * 8 + j;
#pragma unroll
        for (int ks = 0; ks < 2; ks++)
            offA[mt][ks] = 4u * swz(rowA, ks * 8 + (mg >> 1) * 4);
    }
#pragma unroll
    for (int p = 0; p < 2; p++) {
        const int rowB = wn * 32 + p * 16 + (mg >> 1) * 8 + j;
#pragma unroll
        for (int ks = 0; ks < 2; ks++)
            offB[p][ks] = 4u * swz(rowB, ks * 8 + (mg & 1) * 4);
    }

    int acc[4][4][4];
#pragma unroll
    for (int i = 0; i < 4; i++)
#pragma unroll
        for (int jj = 0; jj < 4; jj++)
#pragma unroll
            for (int k = 0; k < 4; k++) acc[i][jj][k] = 0;

    load_stage(sbase, xp, m0, n0, 0, 0, tid, xmode);
    load_stage(sbase, xp, m0, n0, 1, 1, tid, xmode);

    uint32_t af[2][4];                 // ping-pong A fragments
    uint32_t bf0[4][2], bf1[4][2];     // B fragments for ks=0 / ks=1

#pragma unroll
    for (int kt = 0; kt < KTILES; kt++) {
        if (kt < KTILES - 1) asm volatile("cp.async.wait_group 1;" ::: "memory");
        else                 asm volatile("cp.async.wait_group 0;" ::: "memory");
        __syncthreads();

        if (kt + 2 < KTILES)
            load_stage(sbase, xp, m0, n0, (kt + 2) % NSTG, kt + 2, tid, xmode);

        const uint32_t aB = sbase + (uint32_t)(kt % NSTG) * STG_BYTES;
        const uint32_t bB = aB + BM * BK;

        LDSM4(bf0[0][0], bf0[0][1], bf0[1][0], bf0[1][1], bB + offB[0][0]);
        LDSM4(bf0[2][0], bf0[2][1], bf0[3][0], bf0[3][1], bB + offB[1][0]);
        LDSM4(af[0][0], af[0][1], af[0][2], af[0][3],     aB + offA[0][0]);

        LDSM4(af[1][0], af[1][1], af[1][2], af[1][3], aB + offA[1][0]);
        MMA_ROW(acc[0], af[0], bf0);
        LDSM4(af[0][0], af[0][1], af[0][2], af[0][3], aB + offA[2][0]);
        MMA_ROW(acc[1], af[1], bf0);
        LDSM4(af[1][0], af[1][1], af[1][2], af[1][3], aB + offA[3][0]);
        MMA_ROW(acc[2], af[0], bf0);
        LDSM4(bf1[0][0], bf1[0][1], bf1[1][0], bf1[1][1], bB + offB[0][1]);
        LDSM4(bf1[2][0], bf1[2][1], bf1[3][0], bf1[3][1], bB + offB[1][1]);
        LDSM4(af[0][0], af[0][1], af[0][2], af[0][3],     aB + offA[0][1]);
        MMA_ROW(acc[3], af[1], bf0);

        LDSM4(af[1][0], af[1][1], af[1][2], af[1][3], aB + offA[1][1]);
        MMA_ROW(acc[0], af[0], bf1);
        LDSM4(af[0][0], af[0][1], af[0][2], af[0][3], aB + offA[2][1]);
        MMA_ROW(acc[1], af[1], bf1);
        LDSM4(af[1][0], af[1][1], af[1][2], af[1][3], aB + offA[3][1]);
        MMA_ROW(acc[2], af[0], bf1);
        MMA_ROW(acc[3], af[1], bf1);
    }

    // epilogue: dequant + bias + round-half-even + clamp, fp32 stores
    const int bmode = g_bmode;                 // one cached load
    const float alpha = *alpha_p;
#pragma unroll
    for (int mt = 0; mt < 4; mt++) {
        const int row = m0 + wm * 64 + mt * 16 + r;
#pragma unroll
        for (int nt = 0; nt < 4; nt++) {
            const int col = n0 + wn * 32 + nt * 8 + q * 2;
            float b0, b1;
            if (bmode == 0) {
                b0 = ((const float*)bias_p)[col];
                b1 = ((const float*)bias_p)[col + 1];
            } else {
                b0 = __half2float(((const __half*)bias_p)[col]);
                b1 = __half2float(((const __half*)bias_p)[col + 1]);
            }
            float2 v0, v1;
            v0.x = quantf(acc[mt][nt][0], alpha, b0);
            v0.y = quantf(acc[mt][nt][1], alpha, b1);
            v1.x = quantf(acc[mt][nt][2], alpha, b0);
            v1.y = quantf(acc[mt][nt][3], alpha, b1);
            *reinterpret_cast<float2*>(out + (size_t)row * ND + col)       = v0;
            *reinterpret_cast<float2*>(out + (size_t)(row + 8) * ND + col) = v1;
        }
    }
}

// ===========================================================================
extern "C" void kernel_launch(void* const* d_in, const int* in_sizes, int n_in,
                              void* d_out, int out_size) {
    const void* x     = d_in[0];
    const void* w     = d_in[1];
    const void* bias  = d_in[2];
    const float* alpha = (const float*)d_in[3];
    float* out = (float*)d_out;

    const int M = in_sizes[0] / KD;              // 32768

    prep_w<<<NWT, 256>>>(w, (const uint32_t*)bias);

    gemm_q8<<<dim3(ND / BN, M / BM), 256>>>(x, bias, alpha, out);
}

// round 16
// speedup vs baseline: 2.2568x; 2.2568x over previous
#include <cuda_runtime.h>
#include <cuda_fp16.h>
#include <stdint.h>

#define KD 768
#define ND 768
#define MMAX 32768

#define BM 128
#define BN 128
#define BK 64
#define KTILES (KD / BK)                // 12
#define NSTG 3
#define STG_BYTES (BM * BK + BN * BK)   // 16384
#define NWT 576                         // one 32x32 weight tile per block

// Scratch (device globals — no runtime allocation).
__device__ int8_t g_X8[(size_t)MMAX * KD];
__device__ int8_t g_Wt[ND * KD];
__device__ int    g_bmode;              // bias dtype: 0=f32, 1=f16

// ===========================================================================
// dtype predicates (fixed 64-word sample -> identical mode in every block)
// mode: 0 = f32-of-ints, 1 = int32, 2 = packed int8.
// ===========================================================================
__device__ __forceinline__ bool ok_f32_int(uint32_t u) {
    float f = __uint_as_float(u);
    return isfinite(f) && f == rintf(f) && fabsf(f) <= 127.f;
}
__device__ __forceinline__ bool ok_i32(uint32_t u) {
    int v = (int)u;
    return v >= -128 && v <= 127;
}

// Convert x elements [idx, idx+16) into g_X8 under mode. Streaming reads use
// evict-first (__ldcs): x is read exactly once; keep L2 for g_X8/g_Wt.
__device__ __forceinline__ void conv16(const void* __restrict__ xp, size_t idx, int mode) {
    if (mode == 2) {
        *reinterpret_cast<int4*>(&g_X8[idx]) =
            __ldcs(reinterpret_cast<const int4*>((const int8_t*)xp + idx));
        return;
    }
    int8_t o[16];
    if (mode == 0) {
        const float4* f = reinterpret_cast<const float4*>((const float*)xp + idx);
#pragma unroll
        for (int j = 0; j < 4; j++) {
            float4 v = __ldcs(f + j);
            o[j * 4 + 0] = (int8_t)__float2int_rn(v.x);
            o[j * 4 + 1] = (int8_t)__float2int_rn(v.y);
            o[j * 4 + 2] = (int8_t)__float2int_rn(v.z);
            o[j * 4 + 3] = (int8_t)__float2int_rn(v.w);
        }
    } else {
        const int4* f = reinterpret_cast<const int4*>((const int*)xp + idx);
#pragma unroll
        for (int j = 0; j < 4; j++) {
            int4 v = __ldcs(f + j);
            o[j * 4 + 0] = (int8_t)v.x; o[j * 4 + 1] = (int8_t)v.y;
            o[j * 4 + 2] = (int8_t)v.z; o[j * 4 + 3] = (int8_t)v.w;
        }
    }
    *reinterpret_cast<int4*>(&g_X8[idx]) = *reinterpret_cast<int4*>(o);
}

// ===========================================================================
// prep (single launch, fine-grained):
//   blocks 0..NWT-1      : one 32x32 weight tile each (transpose W -> g_Wt)
//   blocks NWT..NWT+6143 : one 4096-element x slab each (convert -> g_X8)
// Detection cost per block: 1 load + 2 __syncthreads_count.
// ===========================================================================
__global__ __launch_bounds__(256, 2)
void prep(const void* __restrict__ xp, const void* __restrict__ wp,
          const uint32_t* __restrict__ bias_w, int M) {
    const int b = blockIdx.x;
    const int tid = threadIdx.x;
    const bool is_wt = (b < NWT);

    // --- block-cooperative dtype detection (fixed 64-word sample) ---
    const uint32_t* src = is_wt ? (const uint32_t*)wp : (const uint32_t*)xp;
    uint32_t u = (tid < 64) ? src[tid] : 0u;
    const int cf = __syncthreads_count(tid < 64 && ok_f32_int(u));
    const int ci = __syncthreads_count(tid < 64 && ok_i32(u));
    const int mode = (cf >= 58) ? 0 : ((ci >= 58) ? 1 : 2);

    if (is_wt) {
        if (b == 0 && tid == 0) {
            int bcnt = 0;
#pragma unroll
            for (int i = 0; i < 16; i++) {
                float f = __uint_as_float(bias_w[i]);
                bcnt += (isfinite(f) &&
                         (f == 0.f || (fabsf(f) >= 1e-6f && fabsf(f) <= 100.f)));
            }
            g_bmode = (bcnt >= 14) ? 0 : 1;
        }

        __shared__ int8_t t[32][33];
        const int tx = tid & 31, ty = tid >> 5;          // 32 x 8
        const int nb = (b % (ND / 32)) * 32;
        const int kb = (b / (ND / 32)) * 32;
#pragma unroll
        for (int j = 0; j < 32; j += 8) {
            const int kk = kb + ty + j, nn = nb + tx;
            int8_t v;
            if (mode == 0)      v = (int8_t)__float2int_rn(((const float*)wp)[kk * ND + nn]);
            else if (mode == 1) v = (int8_t)(((const int*)wp)[kk * ND + nn]);
            else                v = ((const int8_t*)wp)[kk * ND + nn];
            t[ty + j][tx] = v;
        }
        __syncthreads();
#pragma unroll
        for (int j = 0; j < 32; j += 8)
            g_Wt[(size_t)(nb + ty + j) * KD + kb + tx] = t[tx][ty + j];
        return;
    }

    // x conversion: one 16-element run per thread (fine grain, self-balancing)
    const size_t n = (size_t)M * KD;
    const size_t idx = ((size_t)(b - NWT) * 256 + tid) * 16;
    if (idx < n) conv16(xp, idx, mode);
}

// ===========================================================================
// GEMM helpers (round-9/13 measured-best mainloop, unchanged)
// ===========================================================================
__device__ __forceinline__ int swz(int row, int w) {
    return row * 16 + (w ^ (((row >> 1) & 3) << 2));
}

__device__ __forceinline__ float quantf(int acc, float alpha, float b) {
    float v = __fadd_rn(__fmul_rn((float)acc, alpha), b);
    float f = rintf(v);
    return fminf(fmaxf(f, -128.f), 127.f);
}

#define LDSM4(r0, r1, r2, r3, addr) \
    asm volatile("ldmatrix.sync.aligned.m8n8.x4.shared.b16 {%0,%1,%2,%3}, [%4];" \
                 : "=r"(r0), "=r"(r1), "=r"(r2), "=r"(r3) : "r"(addr))

#define MMA_ROW(accrow, a, bfr)                                               \
    do {                                                                      \
        _Pragma("unroll")                                                     \
        for (int nt = 0; nt < 4; nt++) {                                      \
            asm volatile(                                                     \
                "mma.sync.aligned.m16n8k32.row.col.s32.s8.s8.s32 "            \
                "{%0,%1,%2,%3}, {%4,%5,%6,%7}, {%8,%9}, {%0,%1,%2,%3};"       \
                : "+r"((accrow)[nt][0]), "+r"((accrow)[nt][1]),               \
                  "+r"((accrow)[nt][2]), "+r"((accrow)[nt][3])                \
                : "r"((a)[0]), "r"((a)[1]), "r"((a)[2]), "r"((a)[3]),         \
                  "r"((bfr)[nt][0]), "r"((bfr)[nt][1]));                      \
        }                                                                     \
    } while (0)

__device__ __forceinline__ void load_stage(uint32_t sbase, int m0, int n0,
                                           int s, int kt, int tid) {
    const uint32_t sa = sbase + (uint32_t)s * STG_BYTES;
    const uint32_t sb = sa + BM * BK;
    const int8_t* gA = g_X8 + (size_t)m0 * KD + kt * BK;
    const int8_t* gB = g_Wt + (size_t)n0 * KD + kt * BK;
#pragma unroll
    for (int i = 0; i < 2; i++) {
        const int id = tid * 2 + i;            // 0..511
        const int row = id >> 2;               // 0..127
        const int c = id & 3;                  // 16B chunk within 64B row
        const uint32_t off = 4u * swz(row, c * 4);
        asm volatile("cp.async.cg.shared.global [%0], [%1], 16;"
                     :: "r"(sa + off), "l"(gA + (size_t)row * KD + c * 16));
        asm volatile("cp.async.cg.shared.global [%0], [%1], 16;"
                     :: "r"(sb + off), "l"(gB + (size_t)row * KD + c * 16));
    }
    asm volatile("cp.async.commit_group;" ::: "memory");
}

__global__ __launch_bounds__(256, 2)
void gemm_q8(const void* __restrict__ bias_p, const float* __restrict__ alpha_p,
             float* __restrict__ out) {
    __shared__ int8_t smem[NSTG * STG_BYTES];  // 48 KB
    const uint32_t sbase = (uint32_t)__cvta_generic_to_shared(smem);

    const int tid  = threadIdx.x;
    const int lane = tid & 31;
    const int warp = tid >> 5;
    const int wm = warp & 1;                   // 2 warps along M (64 rows)
    const int wn = warp >> 1;                  // 4 warps along N (32 cols)
    const int m0 = blockIdx.y * BM;
    const int n0 = blockIdx.x * BN;
    const int r = lane >> 2;
    const int q = lane & 3;

    // Per-lane swizzled ldmatrix offsets (reused every k-tile).
    const int j  = lane & 7;
    const int mg = lane >> 3;
    uint32_t offA[4][2], offB[2][2];
#pragma unroll
    for (int mt = 0; mt < 4; mt++) {
        const int rowA = wm * 64 + mt * 16 + (mg & 1) * 8 + j;
#pragma unroll
        for (int ks = 0; ks < 2; ks++)
            offA[mt][ks] = 4u * swz(rowA, ks * 8 + (mg >> 1) * 4);
    }
#pragma unroll
    for (int p = 0; p < 2; p++) {
        const int rowB = wn * 32 + p * 16 + (mg >> 1) * 8 + j;
#pragma unroll
        for (int ks = 0; ks < 2; ks++)
            offB[p][ks] = 4u * swz(rowB, ks * 8 + (mg & 1) * 4);
    }

    int acc[4][4][4];
#pragma unroll
    for (int i = 0; i < 4; i++)
#pragma unroll
        for (int jj = 0; jj < 4; jj++)
#pragma unroll
            for (int k = 0; k < 4; k++) acc[i][jj][k] = 0;

    load_stage(sbase, m0, n0, 0, 0, tid);
    load_stage(sbase, m0, n0, 1, 1, tid);

    uint32_t af[2][4];                 // ping-pong A fragments
    uint32_t bf0[4][2], bf1[4][2];     // B fragments for ks=0 / ks=1

#pragma unroll
    for (int kt = 0; kt < KTILES; kt++) {
        if (kt < KTILES - 1) asm volatile("cp.async.wait_group 1;" ::: "memory");
        else                 asm volatile("cp.async.wait_group 0;" ::: "memory");
        __syncthreads();

        if (kt + 2 < KTILES)
            load_stage(sbase, m0, n0, (kt + 2) % NSTG, kt + 2, tid);

        const uint32_t aB = sbase + (uint32_t)(kt % NSTG) * STG_BYTES;
        const uint32_t bB = aB + BM * BK;

        LDSM4(bf0[0][0], bf0[0][1], bf0[1][0], bf0[1][1], bB + offB[0][0]);
        LDSM4(bf0[2][0], bf0[2][1], bf0[3][0], bf0[3][1], bB + offB[1][0]);
        LDSM4(af[0][0], af[0][1], af[0][2], af[0][3],     aB + offA[0][0]);

        LDSM4(af[1][0], af[1][1], af[1][2], af[1][3], aB + offA[1][0]);
        MMA_ROW(acc[0], af[0], bf0);
        LDSM4(af[0][0], af[0][1], af[0][2], af[0][3], aB + offA[2][0]);
        MMA_ROW(acc[1], af[1], bf0);
        LDSM4(af[1][0], af[1][1], af[1][2], af[1][3], aB + offA[3][0]);
        MMA_ROW(acc[2], af[0], bf0);
        LDSM4(bf1[0][0], bf1[0][1], bf1[1][0], bf1[1][1], bB + offB[0][1]);
        LDSM4(bf1[2][0], bf1[2][1], bf1[3][0], bf1[3][1], bB + offB[1][1]);
        LDSM4(af[0][0], af[0][1], af[0][2], af[0][3],     aB + offA[0][1]);
        MMA_ROW(acc[3], af[1], bf0);

        LDSM4(af[1][0], af[1][1], af[1][2], af[1][3], aB + offA[1][1]);
        MMA_ROW(acc[0], af[0], bf1);
        LDSM4(af[0][0], af[0][1], af[0][2], af[0][3], aB + offA[2][1]);
        MMA_ROW(acc[1], af[1], bf1);
        LDSM4(af[1][0], af[1][1], af[1][2], af[1][3], aB + offA[3][1]);
        MMA_ROW(acc[2], af[0], bf1);
        MMA_ROW(acc[3], af[1], bf1);
    }

    // epilogue: dequant + bias + round-half-even + clamp, fp32 stores
    const int bmode = g_bmode;                 // one cached load
    const float alpha = *alpha_p;
#pragma unroll
    for (int mt = 0; mt < 4; mt++) {
        const int row = m0 + wm * 64 + mt * 16 + r;
#pragma unroll
        for (int nt = 0; nt < 4; nt++) {
            const int col = n0 + wn * 32 + nt * 8 + q * 2;
            float b0, b1;
            if (bmode == 0) {
                b0 = ((const float*)bias_p)[col];
                b1 = ((const float*)bias_p)[col + 1];
            } else {
                b0 = __half2float(((const __half*)bias_p)[col]);
                b1 = __half2float(((const __half*)bias_p)[col + 1]);
            }
            float2 v0, v1;
            v0.x = quantf(acc[mt][nt][0], alpha, b0);
            v0.y = quantf(acc[mt][nt][1], alpha, b1);
            v1.x = quantf(acc[mt][nt][2], alpha, b0);
            v1.y = quantf(acc[mt][nt][3], alpha, b1);
            *reinterpret_cast<float2*>(out + (size_t)row * ND + col)       = v0;
            *reinterpret_cast<float2*>(out + (size_t)(row + 8) * ND + col) = v1;
        }
    }
}

// ===========================================================================
extern "C" void kernel_launch(void* const* d_in, const int* in_sizes, int n_in,
                              void* d_out, int out_size) {
    const void* x     = d_in[0];
    const void* w     = d_in[1];
    const void* bias  = d_in[2];
    const float* alpha = (const float*)d_in[3];
    float* out = (float*)d_out;

    const int M = in_sizes[0] / KD;              // 32768

    const size_t n = (size_t)M * KD;
    const unsigned convBlocks = (unsigned)((n / 16 + 255) / 256);   // 6144
    prep<<<NWT + convBlocks, 256>>>(x, w, (const uint32_t*)bias, M);

    gemm_q8<<<dim3(ND / BN, M / BM), 256>>>(bias, alpha, out);
}

// round 17
// speedup vs baseline: 2.2761x; 1.0086x over previous
#include <cuda_runtime.h>
#include <cuda_fp16.h>
#include <stdint.h>

#define KD 768
#define ND 768
#define MMAX 32768

#define BM 128
#define BN 128
#define BK 64
#define KTILES (KD / BK)                // 12
#define NSTG 3
#define STG_BYTES (BM * BK + BN * BK)   // 16384
#define NWT 576                         // one 32x32 weight tile per block

// Scratch (device globals — no runtime allocation).
__device__ int8_t g_X8[(size_t)MMAX * KD];
__device__ int8_t g_Wt[ND * KD];
__device__ int    g_bmode;              // bias dtype: 0=f32, 1=f16

// ===========================================================================
// dtype predicates (fixed 64-word sample -> identical mode in every block)
// mode: 0 = f32-of-ints, 1 = int32, 2 = packed int8.
// ===========================================================================
__device__ __forceinline__ bool ok_f32_int(uint32_t u) {
    float f = __uint_as_float(u);
    return isfinite(f) && f == rintf(f) && fabsf(f) <= 127.f;
}
__device__ __forceinline__ bool ok_i32(uint32_t u) {
    int v = (int)u;
    return v >= -128 && v <= 127;
}

// Convert x elements [idx, idx+16) into g_X8 under mode. Streaming reads use
// evict-first (__ldcs): x is read exactly once; keep L2 for g_X8/g_Wt.
__device__ __forceinline__ void conv16(const void* __restrict__ xp, size_t idx, int mode) {
    if (mode == 2) {
        *reinterpret_cast<int4*>(&g_X8[idx]) =
            __ldcs(reinterpret_cast<const int4*>((const int8_t*)xp + idx));
        return;
    }
    int8_t o[16];
    if (mode == 0) {
        const float4* f = reinterpret_cast<const float4*>((const float*)xp + idx);
#pragma unroll
        for (int j = 0; j < 4; j++) {
            float4 v = __ldcs(f + j);
            o[j * 4 + 0] = (int8_t)__float2int_rn(v.x);
            o[j * 4 + 1] = (int8_t)__float2int_rn(v.y);
            o[j * 4 + 2] = (int8_t)__float2int_rn(v.z);
            o[j * 4 + 3] = (int8_t)__float2int_rn(v.w);
        }
    } else {
        const int4* f = reinterpret_cast<const int4*>((const int*)xp + idx);
#pragma unroll
        for (int j = 0; j < 4; j++) {
            int4 v = __ldcs(f + j);
            o[j * 4 + 0] = (int8_t)v.x; o[j * 4 + 1] = (int8_t)v.y;
            o[j * 4 + 2] = (int8_t)v.z; o[j * 4 + 3] = (int8_t)v.w;
        }
    }
    *reinterpret_cast<int4*>(&g_X8[idx]) = *reinterpret_cast<int4*>(o);
}

// ===========================================================================
// prep (single launch, fine-grained):
//   blocks 0..NWT-1      : one 32x32 weight tile each (transpose W -> g_Wt)
//   blocks NWT..NWT+6143 : one 4096-element x slab each (convert -> g_X8)
// Detection cost per block: 1 load + 2 __syncthreads_count.
// ===========================================================================
__global__ __launch_bounds__(256, 2)
void prep(const void* __restrict__ xp, const void* __restrict__ wp,
          const uint32_t* __restrict__ bias_w, int M) {
    const int b = blockIdx.x;
    const int tid = threadIdx.x;
    const bool is_wt = (b < NWT);

    // --- block-cooperative dtype detection (fixed 64-word sample) ---
    const uint32_t* src = is_wt ? (const uint32_t*)wp : (const uint32_t*)xp;
    uint32_t u = (tid < 64) ? src[tid] : 0u;
    const int cf = __syncthreads_count(tid < 64 && ok_f32_int(u));
    const int ci = __syncthreads_count(tid < 64 && ok_i32(u));
    const int mode = (cf >= 58) ? 0 : ((ci >= 58) ? 1 : 2);

    if (is_wt) {
        if (b == 0 && tid == 0) {
            int bcnt = 0;
#pragma unroll
            for (int i = 0; i < 16; i++) {
                float f = __uint_as_float(bias_w[i]);
                bcnt += (isfinite(f) &&
                         (f == 0.f || (fabsf(f) >= 1e-6f && fabsf(f) <= 100.f)));
            }
            g_bmode = (bcnt >= 14) ? 0 : 1;
        }

        __shared__ int8_t t[32][33];
        const int tx = tid & 31, ty = tid >> 5;          // 32 x 8
        const int nb = (b % (ND / 32)) * 32;
        const int kb = (b / (ND / 32)) * 32;
#pragma unroll
        for (int j = 0; j < 32; j += 8) {
            const int kk = kb + ty + j, nn = nb + tx;
            int8_t v;
            if (mode == 0)      v = (int8_t)__float2int_rn(((const float*)wp)[kk * ND + nn]);
            else if (mode == 1) v = (int8_t)(((const int*)wp)[kk * ND + nn]);
            else                v = ((const int8_t*)wp)[kk * ND + nn];
            t[ty + j][tx] = v;
        }
        __syncthreads();
#pragma unroll
        for (int j = 0; j < 32; j += 8)
            g_Wt[(size_t)(nb + ty + j) * KD + kb + tx] = t[tx][ty + j];
        return;
    }

    // x conversion: one 16-element run per thread (fine grain, self-balancing)
    const size_t n = (size_t)M * KD;
    const size_t idx = ((size_t)(b - NWT) * 256 + tid) * 16;
    if (idx < n) conv16(xp, idx, mode);
}

// ===========================================================================
// GEMM helpers (measured-best mainloop, unchanged)
// ===========================================================================
__device__ __forceinline__ int swz(int row, int w) {
    return row * 16 + (w ^ (((row >> 1) & 3) << 2));
}

__device__ __forceinline__ float quantf(int acc, float alpha, float b) {
    float v = __fadd_rn(__fmul_rn((float)acc, alpha), b);
    float f = rintf(v);
    return fminf(fmaxf(f, -128.f), 127.f);
}

#define LDSM4(r0, r1, r2, r3, addr) \
    asm volatile("ldmatrix.sync.aligned.m8n8.x4.shared.b16 {%0,%1,%2,%3}, [%4];" \
                 : "=r"(r0), "=r"(r1), "=r"(r2), "=r"(r3) : "r"(addr))

#define MMA_ROW(accrow, a, bfr)                                               \
    do {                                                                      \
        _Pragma("unroll")                                                     \
        for (int nt = 0; nt < 4; nt++) {                                      \
            asm volatile(                                                     \
                "mma.sync.aligned.m16n8k32.row.col.s32.s8.s8.s32 "            \
                "{%0,%1,%2,%3}, {%4,%5,%6,%7}, {%8,%9}, {%0,%1,%2,%3};"       \
                : "+r"((accrow)[nt][0]), "+r"((accrow)[nt][1]),               \
                  "+r"((accrow)[nt][2]), "+r"((accrow)[nt][3])                \
                : "r"((a)[0]), "r"((a)[1]), "r"((a)[2]), "r"((a)[3]),         \
                  "r"((bfr)[nt][0]), "r"((bfr)[nt][1]));                      \
        }                                                                     \
    } while (0)

__device__ __forceinline__ void load_stage(uint32_t sbase, int m0, int n0,
                                           int s, int kt, int tid) {
    const uint32_t sa = sbase + (uint32_t)s * STG_BYTES;
    const uint32_t sb = sa + BM * BK;
    const int8_t* gA = g_X8 + (size_t)m0 * KD + kt * BK;
    const int8_t* gB = g_Wt + (size_t)n0 * KD + kt * BK;
#pragma unroll
    for (int i = 0; i < 2; i++) {
        const int id = tid * 2 + i;            // 0..511
        const int row = id >> 2;               // 0..127
        const int c = id & 3;                  // 16B chunk within 64B row
        const uint32_t off = 4u * swz(row, c * 4);
        asm volatile("cp.async.cg.shared.global [%0], [%1], 16;"
                     :: "r"(sa + off), "l"(gA + (size_t)row * KD + c * 16));
        asm volatile("cp.async.cg.shared.global [%0], [%1], 16;"
                     :: "r"(sb + off), "l"(gB + (size_t)row * KD + c * 16));
    }
    asm volatile("cp.async.commit_group;" ::: "memory");
}

__global__ __launch_bounds__(256, 2)
void gemm_q8(const void* __restrict__ bias_p, const float* __restrict__ alpha_p,
             float* __restrict__ out) {
    __shared__ int8_t smem[NSTG * STG_BYTES];  // 48 KB
    const uint32_t sbase = (uint32_t)__cvta_generic_to_shared(smem);

    const int tid  = threadIdx.x;
    const int lane = tid & 31;
    const int warp = tid >> 5;
    const int wm = warp & 1;                   // 2 warps along M (64 rows)
    const int wn = warp >> 1;                  // 4 warps along N (32 cols)
    const int m0 = blockIdx.y * BM;
    const int n0 = blockIdx.x * BN;
    const int r = lane >> 2;
    const int q = lane & 3;

    // Per-lane swizzled ldmatrix offsets (reused every k-tile).
    const int j  = lane & 7;
    const int mg = lane >> 3;
    uint32_t offA[4][2], offB[2][2];
#pragma unroll
    for (int mt = 0; mt < 4; mt++) {
        const int rowA = wm * 64 + mt * 16 + (mg & 1) * 8 + j;
#pragma unroll
        for (int ks = 0; ks < 2; ks++)
            offA[mt][ks] = 4u * swz(rowA, ks * 8 + (mg >> 1) * 4);
    }
#pragma unroll
    for (int p = 0; p < 2; p++) {
        const int rowB = wn * 32 + p * 16 + (mg >> 1) * 8 + j;
#pragma unroll
        for (int ks = 0; ks < 2; ks++)
            offB[p][ks] = 4u * swz(rowB, ks * 8 + (mg & 1) * 4);
    }

    int acc[4][4][4];
#pragma unroll
    for (int i = 0; i < 4; i++)
#pragma unroll
        for (int jj = 0; jj < 4; jj++)
#pragma unroll
            for (int k = 0; k < 4; k++) acc[i][jj][k] = 0;

    load_stage(sbase, m0, n0, 0, 0, tid);
    load_stage(sbase, m0, n0, 1, 1, tid);

    uint32_t af[2][4];                 // ping-pong A fragments
    uint32_t bf0[4][2], bf1[4][2];     // B fragments for ks=0 / ks=1

#pragma unroll
    for (int kt = 0; kt < KTILES; kt++) {
        if (kt < KTILES - 1) asm volatile("cp.async.wait_group 1;" ::: "memory");
        else                 asm volatile("cp.async.wait_group 0;" ::: "memory");
        __syncthreads();

        if (kt + 2 < KTILES)
            load_stage(sbase, m0, n0, (kt + 2) % NSTG, kt + 2, tid);

        const uint32_t aB = sbase + (uint32_t)(kt % NSTG) * STG_BYTES;
        const uint32_t bB = aB + BM * BK;

        LDSM4(bf0[0][0], bf0[0][1], bf0[1][0], bf0[1][1], bB + offB[0][0]);
        LDSM4(bf0[2][0], bf0[2][1], bf0[3][0], bf0[3][1], bB + offB[1][0]);
        LDSM4(af[0][0], af[0][1], af[0][2], af[0][3],     aB + offA[0][0]);

        LDSM4(af[1][0], af[1][1], af[1][2], af[1][3], aB + offA[1][0]);
        MMA_ROW(acc[0], af[0], bf0);
        LDSM4(af[0][0], af[0][1], af[0][2], af[0][3], aB + offA[2][0]);
        MMA_ROW(acc[1], af[1], bf0);
        LDSM4(af[1][0], af[1][1], af[1][2], af[1][3], aB + offA[3][0]);
        MMA_ROW(acc[2], af[0], bf0);
        LDSM4(bf1[0][0], bf1[0][1], bf1[1][0], bf1[1][1], bB + offB[0][1]);
        LDSM4(bf1[2][0], bf1[2][1], bf1[3][0], bf1[3][1], bB + offB[1][1]);
        LDSM4(af[0][0], af[0][1], af[0][2], af[0][3],     aB + offA[0][1]);
        MMA_ROW(acc[3], af[1], bf0);

        LDSM4(af[1][0], af[1][1], af[1][2], af[1][3], aB + offA[1][1]);
        MMA_ROW(acc[0], af[0], bf1);
        LDSM4(af[0][0], af[0][1], af[0][2], af[0][3], aB + offA[2][1]);
        MMA_ROW(acc[1], af[1], bf1);
        LDSM4(af[1][0], af[1][1], af[1][2], af[1][3], aB + offA[3][1]);
        MMA_ROW(acc[2], af[0], bf1);
        MMA_ROW(acc[3], af[1], bf1);
    }

    // epilogue: dequant + bias + round-half-even + clamp, fp32 stores.
    // Bias depends only on nt -> hoist the 8 bias floats out of the mt loop.
    const int bmode = g_bmode;                 // one cached load
    const float alpha = *alpha_p;

    float bv[4][2];
#pragma unroll
    for (int nt = 0; nt < 4; nt++) {
        const int col = n0 + wn * 32 + nt * 8 + q * 2;
        if (bmode == 0) {
            bv[nt][0] = ((const float*)bias_p)[col];
            bv[nt][1] = ((const float*)bias_p)[col + 1];
        } else {
            bv[nt][0] = __half2float(((const __half*)bias_p)[col]);
            bv[nt][1] = __half2float(((const __half*)bias_p)[col + 1]);
        }
    }

#pragma unroll
    for (int nt = 0; nt < 4; nt++) {
        const int col = n0 + wn * 32 + nt * 8 + q * 2;
        const float b0 = bv[nt][0], b1 = bv[nt][1];
#pragma unroll
        for (int mt = 0; mt < 4; mt++) {
            const int row = m0 + wm * 64 + mt * 16 + r;
            float2 v0, v1;
            v0.x = quantf(acc[mt][nt][0], alpha, b0);
            v0.y = quantf(acc[mt][nt][1], alpha, b1);
            v1.x = quantf(acc[mt][nt][2], alpha, b0);
            v1.y = quantf(acc[mt][nt][3], alpha, b1);
            *reinterpret_cast<float2*>(out + (size_t)row * ND + col)       = v0;
            *reinterpret_cast<float2*>(out + (size_t)(row + 8) * ND + col) = v1;
        }
    }
}

// ===========================================================================
extern "C" void kernel_launch(void* const* d_in, const int* in_sizes, int n_in,
                              void* d_out, int out_size) {
    const void* x     = d_in[0];
    const void* w     = d_in[1];
    const void* bias  = d_in[2];
    const float* alpha = (const float*)d_in[3];
    float* out = (float*)d_out;

    const int M = in_sizes[0] / KD;              // 32768

    const size_t n = (size_t)M * KD;
    const unsigned convBlocks = (unsigned)((n / 16 + 255) / 256);   // 6144
    prep<<<NWT + convBlocks, 256>>>(x, w, (const uint32_t*)bias, M);

    gemm_q8<<<dim3(ND / BN, M / BM), 256>>>(bias, alpha, out);
}